// round 12
// baseline (speedup 1.0000x reference)
#include <cuda_runtime.h>

// PGJANET recurrent scan: B=256, T=2048, H=64, O=2.
// 128 blocks x 256 threads, 2 elems/block, ASYMMETRIC roles, 3 barriers/step:
//  LO (warps 0-3): seg1 a/p1/p2 partial dots (32-k slices, 96 wregs) ->
//                  seg2 u-finalize (MUFU tanh);  warps 2-3 emit y in seg3.
//  HI (warps 4-7): seg1 fh/gh partial dots (64 wregs) ->
//                  seg3 FULL fu/gu u-row dots in-register (128 wregs) fused
//                  with h-finalize (exact sigmoid/tanh) -> ping-pong hbuf.
// Scalar FFMA only; smem partials unpacked (float); no shuffles in recurrence.

#define TB 2048

__device__ __forceinline__ float sigf(float v) {
    return __fdividef(1.f, 1.f + __expf(-v));
}
__device__ __forceinline__ float tanhfast(float v) {
    return fmaf(2.f, sigf(2.f * v), -1.f);
}
__device__ __forceinline__ float tanhmufu(float v) {
    float r; asm("tanh.approx.f32 %0, %1;" : "=f"(r) : "f"(v)); return r;
}

__global__ void __launch_bounds__(256, 1)
pgjanet_kernel(const float* __restrict__ x,
               const float* __restrict__ h0,
               const float* __restrict__ Wa,  const float* __restrict__ ba,
               const float* __restrict__ Wp1, const float* __restrict__ bp1,
               const float* __restrict__ Wp2, const float* __restrict__ bp2,
               const float* __restrict__ Wf,  const float* __restrict__ bf,
               const float* __restrict__ Wg,  const float* __restrict__ bg,
               const float* __restrict__ Wo,  const float* __restrict__ bo,
               float* __restrict__ out)
{
    __shared__ __align__(16) float2 xb[2][TB];         // 32 KB
    __shared__ __align__(16) float hbuf[2][2][64];     // ping-pong [pp][e][j]
    __shared__ __align__(16) float ubuf[2][64];        // [e][j]
    __shared__ __align__(16) float part1[3][2][2][64]; // [a/p1/p2][e][slice][j]
    __shared__ __align__(16) float parth[2][2][2][64]; // [f/g][e][slice][j]

    const int tid  = threadIdx.x;
    const int lane = tid & 31;
    const int wid  = tid >> 5;
    const bool LO  = (tid < 128);
    const int j    = tid & 63;          // hidden unit
    const int sl   = (tid >> 6) & 1;    // 32-k slice within role half
    const int b0   = blockIdx.x * 2;

    // ---- weights ----
    float wa[32], wp1[32], wp2[32];         // LO only
    float wfh[32], wgh[32], wfu[64], wgu[64]; // HI only
    if (LO) {
        const float* A = Wa  + j * 65 + sl * 32;
        const float* P = Wp1 + j * 65 + sl * 32;
        const float* Q = Wp2 + j * 65 + sl * 32;
        #pragma unroll
        for (int i = 0; i < 32; i++) { wa[i] = A[i]; wp1[i] = P[i]; wp2[i] = Q[i]; }
    } else {
        const float* F = Wf + j * 128 + sl * 32;
        const float* G = Wg + j * 128 + sl * 32;
        #pragma unroll
        for (int i = 0; i < 32; i++) { wfh[i] = F[i]; wgh[i] = G[i]; }
        const float* Fu = Wf + j * 128 + 64;
        const float* Gu = Wg + j * 128 + 64;
        #pragma unroll
        for (int i = 0; i < 64; i++) { wfu[i] = Fu[i]; wgu[i] = Gu[i]; }
    }

    // ---- finalize constants ----
    float walast = 0.f, w1last = 0.f, w2last = 0.f, ba_r = 0.f, b1_r = 0.f, b2_r = 0.f;
    if (LO) {                               // u-finalize: (e = tid>>6, j)
        walast = Wa [j * 65 + 64]; ba_r = ba [j];
        w1last = Wp1[j * 65 + 64]; b1_r = bp1[j];
        w2last = Wp2[j * 65 + 64]; b2_r = bp2[j];
    }
    float bf_r = 0.f, bg_r = 0.f;
    if (!LO) { bf_r = bf[j]; bg_r = bg[j]; }   // h-finalize: (e = sl, j)
    float woA0 = 0.f, woB0 = 0.f, woA1 = 0.f, woB1 = 0.f, bo0 = 0.f, bo1 = 0.f;
    if (wid == 2 || wid == 3) {             // y-output: warp 2 -> e0, warp 3 -> e1
        woA0 = Wo[lane];      woB0 = Wo[lane + 32];
        woA1 = Wo[64 + lane]; woB1 = Wo[96 + lane];
        bo0 = bo[0]; bo1 = bo[1];
    }

    // ---- preload x + h0 ----
    {
        const float2* xg0 = (const float2*)x + (size_t)b0 * TB;
        const float2* xg1 = (const float2*)x + (size_t)(b0 + 1) * TB;
        for (int i = tid; i < TB; i += 256) { xb[0][i] = xg0[i]; xb[1][i] = xg1[i]; }
    }
    if (tid < 128) hbuf[0][tid >> 6][j] = h0[(size_t)(b0 + (tid >> 6)) * 64 + j];
    __syncthreads();

    #pragma unroll 1
    for (int t = 0; t < TB; t++) {
        const int cur = t & 1, nxt = cur ^ 1;

        // ==== seg1: partial dots over h slice sl, both elems ====
        if (LO) {
            const float4* h0p = (const float4*)&hbuf[cur][0][sl * 32];
            const float4* h1p = (const float4*)&hbuf[cur][1][sl * 32];
            float a0 = 0.f, p0 = 0.f, q0 = 0.f;
            float a1 = 0.f, p1 = 0.f, q1 = 0.f;
            #pragma unroll
            for (int r = 0; r < 8; r++) {
                float4 v0 = h0p[r], v1 = h1p[r];
                #pragma unroll
                for (int c = 0; c < 4; c++) {
                    float w_a = wa[4*r+c], w_p = wp1[4*r+c], w_q = wp2[4*r+c];
                    float e0 = (c==0)?v0.x:(c==1)?v0.y:(c==2)?v0.z:v0.w;
                    float e1 = (c==0)?v1.x:(c==1)?v1.y:(c==2)?v1.z:v1.w;
                    a0 = fmaf(w_a, e0, a0); a1 = fmaf(w_a, e1, a1);
                    p0 = fmaf(w_p, e0, p0); p1 = fmaf(w_p, e1, p1);
                    q0 = fmaf(w_q, e0, q0); q1 = fmaf(w_q, e1, q1);
                }
            }
            part1[0][0][sl][j] = a0;  part1[0][1][sl][j] = a1;
            part1[1][0][sl][j] = p0;  part1[1][1][sl][j] = p1;
            part1[2][0][sl][j] = q0;  part1[2][1][sl][j] = q1;
        } else {
            const float4* h0p = (const float4*)&hbuf[cur][0][sl * 32];
            const float4* h1p = (const float4*)&hbuf[cur][1][sl * 32];
            float f0 = 0.f, g0 = 0.f, f1 = 0.f, g1 = 0.f;
            #pragma unroll
            for (int r = 0; r < 8; r++) {
                float4 v0 = h0p[r], v1 = h1p[r];
                #pragma unroll
                for (int c = 0; c < 4; c++) {
                    float w_f = wfh[4*r+c], w_g = wgh[4*r+c];
                    float e0 = (c==0)?v0.x:(c==1)?v0.y:(c==2)?v0.z:v0.w;
                    float e1 = (c==0)?v1.x:(c==1)?v1.y:(c==2)?v1.z:v1.w;
                    f0 = fmaf(w_f, e0, f0); f1 = fmaf(w_f, e1, f1);
                    g0 = fmaf(w_g, e0, g0); g1 = fmaf(w_g, e1, g1);
                }
            }
            parth[0][0][sl][j] = f0;  parth[0][1][sl][j] = f1;
            parth[1][0][sl][j] = g0;  parth[1][1][sl][j] = g1;
        }
        __syncthreads();   // #1: partials ready

        // ==== seg2: u-finalize (LO, 128 threads: e = tid>>6, j) ====
        if (LO) {
            const int e = tid >> 6;
            float2 xv = xb[e][t];
            float s2 = fmaf(xv.x, xv.x, xv.y * xv.y);
            float ri = rsqrtf(s2);
            float amp, ct, st;
            if (s2 > 0.f) { amp = s2 * ri; ct = xv.x * ri; st = xv.y * ri; }
            else          { amp = 0.f;     ct = 1.f;       st = 0.f; }
            float sa = part1[0][e][0][j] + part1[0][e][1][j];
            float sp = part1[1][e][0][j] + part1[1][e][1][j];
            float sq = part1[2][e][0][j] + part1[2][e][1][j];
            float av  = tanhmufu(fmaf(amp, walast, sa + ba_r));
            float p1v = tanhmufu(fmaf(ct,  w1last, sp + b1_r));
            float p2v = tanhmufu(fmaf(st,  w2last, sq + b2_r));
            ubuf[e][j] = (av - av * av) * (p1v - p1v * p1v) * (p2v - p2v * p2v);
        }
        __syncthreads();   // #2: ubuf ready

        if (!LO) {
            // ==== seg3-HI: full fu/gu dots + fused h-finalize (e = sl) ====
            const float4* up = (const float4*)&ubuf[sl][0];
            float fa = 0.f, fb = 0.f, ga = 0.f, gb = 0.f;
            #pragma unroll
            for (int r = 0; r < 8; r++) {
                float4 va = up[2*r], vb = up[2*r+1];
                fa = fmaf(wfu[8*r+0], va.x, fa); ga = fmaf(wgu[8*r+0], va.x, ga);
                fa = fmaf(wfu[8*r+1], va.y, fa); ga = fmaf(wgu[8*r+1], va.y, ga);
                fa = fmaf(wfu[8*r+2], va.z, fa); ga = fmaf(wgu[8*r+2], va.z, ga);
                fa = fmaf(wfu[8*r+3], va.w, fa); ga = fmaf(wgu[8*r+3], va.w, ga);
                fb = fmaf(wfu[8*r+4], vb.x, fb); gb = fmaf(wgu[8*r+4], vb.x, gb);
                fb = fmaf(wfu[8*r+5], vb.y, fb); gb = fmaf(wgu[8*r+5], vb.y, gb);
                fb = fmaf(wfu[8*r+6], vb.z, fb); gb = fmaf(wgu[8*r+6], vb.z, gb);
                fb = fmaf(wfu[8*r+7], vb.w, fb); gb = fmaf(wgu[8*r+7], vb.w, gb);
            }
            float sf = (fa + fb) + parth[0][sl][0][j] + parth[0][sl][1][j];
            float sg = (ga + gb) + parth[1][sl][0][j] + parth[1][sl][1][j];
            float f = sigf(sf + bf_r);
            float g = tanhfast(sg + bg_r);
            float hold = hbuf[cur][sl][j];
            hbuf[nxt][sl][j] = fmaf(f, hold - g, g);   // f*h + (1-f)*g
        } else if ((wid == 2 || wid == 3) && t > 0) {
            // ==== seg3-LO: y output for step t-1 (reads hbuf[cur] = h after t-1) ====
            const int e = wid - 2;
            float ha = hbuf[cur][e][lane], hb = hbuf[cur][e][lane + 32];
            float y0 = ha * woA0 + hb * woB0;
            float y1 = ha * woA1 + hb * woB1;
            #pragma unroll
            for (int off = 16; off; off >>= 1) {
                y0 += __shfl_xor_sync(~0u, y0, off);
                y1 += __shfl_xor_sync(~0u, y1, off);
            }
            if (lane == 0)
                ((float2*)out)[(size_t)(b0 + e) * TB + (t - 1)] =
                    make_float2(y0 + bo0, y1 + bo1);
        }
        __syncthreads();   // #3: hbuf[nxt] ready
    }

    // ---- epilogue: y for t = TB-1 (hbuf[TB & 1] holds final state) ----
    if (wid == 2 || wid == 3) {
        const int e = wid - 2;
        const int fin = TB & 1;
        float ha = hbuf[fin][e][lane], hb = hbuf[fin][e][lane + 32];
        float y0 = ha * woA0 + hb * woB0;
        float y1 = ha * woA1 + hb * woB1;
        #pragma unroll
        for (int off = 16; off; off >>= 1) {
            y0 += __shfl_xor_sync(~0u, y0, off);
            y1 += __shfl_xor_sync(~0u, y1, off);
        }
        if (lane == 0)
            ((float2*)out)[(size_t)(b0 + e) * TB + (TB - 1)] =
                make_float2(y0 + bo0, y1 + bo1);
    }
}

extern "C" void kernel_launch(void* const* d_in, const int* in_sizes, int n_in,
                              void* d_out, int out_size)
{
    const float* x   = (const float*)d_in[0];
    const float* h0  = (const float*)d_in[1];
    const float* Wa  = (const float*)d_in[2];
    const float* ba  = (const float*)d_in[3];
    const float* Wp1 = (const float*)d_in[4];
    const float* bp1 = (const float*)d_in[5];
    const float* Wp2 = (const float*)d_in[6];
    const float* bp2 = (const float*)d_in[7];
    const float* Wf  = (const float*)d_in[8];
    const float* bf  = (const float*)d_in[9];
    const float* Wg  = (const float*)d_in[10];
    const float* bg  = (const float*)d_in[11];
    const float* Wo  = (const float*)d_in[12];
    const float* bo  = (const float*)d_in[13];
    float* out = (float*)d_out;

    pgjanet_kernel<<<128, 256>>>(x, h0, Wa, ba, Wp1, bp1, Wp2, bp2,
                                 Wf, bf, Wg, bg, Wo, bo, out);
}

// round 13
// speedup vs baseline: 1.6030x; 1.6030x over previous
#include <cuda_runtime.h>

// PGJANET recurrent scan: B=256, T=2048, H=64, O=2.
// R4 structure VERBATIM (validated fastest: 128 blocks x 256 threads, 2 batch
// elements per block, 4 barriers/step, scalar-float smem partials, scalar
// FFMA, 112 weight floats in registers, y overlapped on warps 6-7).
// Single change vs R4: all finalize transcendentals use tanh.approx.f32
// (1 MUFU) instead of __expf/__fdividef chains:
//   tanh(x)    -> tanh.approx.f32
//   sigmoid(x) -> 0.5*tanh.approx(x/2) + 0.5

#define TB 2048

__device__ __forceinline__ float tanhmufu(float v) {
    float r; asm("tanh.approx.f32 %0, %1;" : "=f"(r) : "f"(v)); return r;
}
__device__ __forceinline__ float sigmufu(float v) {
    return fmaf(0.5f, tanhmufu(0.5f * v), 0.5f);
}

__global__ void __launch_bounds__(256, 1)
pgjanet_kernel(const float* __restrict__ x,
               const float* __restrict__ h0,
               const float* __restrict__ Wa,  const float* __restrict__ ba,
               const float* __restrict__ Wp1, const float* __restrict__ bp1,
               const float* __restrict__ Wp2, const float* __restrict__ bp2,
               const float* __restrict__ Wf,  const float* __restrict__ bf,
               const float* __restrict__ Wg,  const float* __restrict__ bg,
               const float* __restrict__ Wo,  const float* __restrict__ bo,
               float* __restrict__ out)
{
    __shared__ __align__(16) float2 xb[2][TB];        // 32 KB
    __shared__ __align__(16) float hbuf[2][64];
    __shared__ __align__(16) float ubuf[2][64];
    __shared__ __align__(16) float part[2][5][4][64]; // [elem][gate][slice][unit]

    const int tid  = threadIdx.x;
    const int lane = tid & 31;
    const int wid  = tid >> 5;
    const int j    = tid & 63;      // hidden unit
    const int s    = tid >> 6;      // k-slice 0..3
    const int b0   = blockIdx.x * 2;

    // ---- weights in registers (112 floats) ----
    float wa[16], wp1[16], wp2[16], wfh[16], wgh[16], wfu[16], wgu[16];
    {
        const float* A = Wa  + j * 65 + s * 16;
        const float* P = Wp1 + j * 65 + s * 16;
        const float* Q = Wp2 + j * 65 + s * 16;
        const float* F = Wf  + j * 128 + s * 16;
        const float* G = Wg  + j * 128 + s * 16;
        #pragma unroll
        for (int i = 0; i < 16; i++) {
            wa[i]  = A[i];  wp1[i] = P[i];  wp2[i] = Q[i];
            wfh[i] = F[i];  wgh[i] = G[i];
            wfu[i] = F[64 + i]; wgu[i] = G[64 + i];
        }
    }

    // ---- finalize constants ----
    // u-finalize: warps 0-3 (tid<128), thread -> (e = tid>>6, j)
    float walast = 0.f, w1last = 0.f, w2last = 0.f, ba_r = 0.f, b1_r = 0.f, b2_r = 0.f;
    if (tid < 128) {
        walast = Wa [j * 65 + 64]; ba_r = ba [j];
        w1last = Wp1[j * 65 + 64]; b1_r = bp1[j];
        w2last = Wp2[j * 65 + 64]; b2_r = bp2[j];
    }
    // h-finalize: warps 4-7 (tid>=128), thread -> (e = (tid>>6)&1, j)
    float bf_r = 0.f, bg_r = 0.f;
    if (tid >= 128) { bf_r = bf[j]; bg_r = bg[j]; }
    // y-output: warps 6,7 -> elem 0,1
    float woA0 = 0.f, woB0 = 0.f, woA1 = 0.f, woB1 = 0.f, bo0 = 0.f, bo1 = 0.f;
    if (wid >= 6) {
        woA0 = Wo[lane];      woB0 = Wo[lane + 32];
        woA1 = Wo[64 + lane]; woB1 = Wo[96 + lane];
        bo0 = bo[0]; bo1 = bo[1];
    }

    // ---- preload x + h0 ----
    {
        const float2* xg0 = (const float2*)x + (size_t)b0 * TB;
        const float2* xg1 = (const float2*)x + (size_t)(b0 + 1) * TB;
        for (int i = tid; i < TB; i += 256) { xb[0][i] = xg0[i]; xb[1][i] = xg1[i]; }
    }
    if (tid < 128) hbuf[tid >> 6][j] = h0[(size_t)(b0 + (tid >> 6)) * 64 + j];
    __syncthreads();

    #pragma unroll 1
    for (int t = 0; t < TB; t++) {
        // ==== phase 1: a/p1/p2 + f/g h-half partial dots (both elems) ====
        {
            const float4* h0p = (const float4*)&hbuf[0][s * 16];
            const float4* h1p = (const float4*)&hbuf[1][s * 16];
            float a0 = 0.f, p0 = 0.f, q0 = 0.f, f0 = 0.f, g0 = 0.f;
            float a1 = 0.f, p1 = 0.f, q1 = 0.f, f1 = 0.f, g1 = 0.f;
            #pragma unroll
            for (int r = 0; r < 4; r++) {
                float4 v0 = h0p[r], v1 = h1p[r];
                #pragma unroll
                for (int c = 0; c < 4; c++) {
                    float w_a = wa[4*r+c], w_p = wp1[4*r+c], w_q = wp2[4*r+c];
                    float w_f = wfh[4*r+c], w_g = wgh[4*r+c];
                    float e0 = (c==0)?v0.x:(c==1)?v0.y:(c==2)?v0.z:v0.w;
                    float e1 = (c==0)?v1.x:(c==1)?v1.y:(c==2)?v1.z:v1.w;
                    a0 = fmaf(w_a, e0, a0); a1 = fmaf(w_a, e1, a1);
                    p0 = fmaf(w_p, e0, p0); p1 = fmaf(w_p, e1, p1);
                    q0 = fmaf(w_q, e0, q0); q1 = fmaf(w_q, e1, q1);
                    f0 = fmaf(w_f, e0, f0); f1 = fmaf(w_f, e1, f1);
                    g0 = fmaf(w_g, e0, g0); g1 = fmaf(w_g, e1, g1);
                }
            }
            part[0][0][s][j] = a0;  part[1][0][s][j] = a1;
            part[0][1][s][j] = p0;  part[1][1][s][j] = p1;
            part[0][2][s][j] = q0;  part[1][2][s][j] = q1;
            part[0][3][s][j] = f0;  part[1][3][s][j] = f1;
            part[0][4][s][j] = g0;  part[1][4][s][j] = g1;
        }
        __syncthreads();

        // ==== u-finalize (warps 0-3) || y output (warps 6-7) ====
        if (tid < 128) {
            const int e = tid >> 6;
            float2 xv = xb[e][t];
            float s2 = fmaf(xv.x, xv.x, xv.y * xv.y);
            float ri = rsqrtf(s2);
            float amp, ct, st;
            if (s2 > 0.f) { amp = s2 * ri; ct = xv.x * ri; st = xv.y * ri; }
            else          { amp = 0.f;     ct = 1.f;       st = 0.f; }
            float sa = part[e][0][0][j] + part[e][0][1][j] + part[e][0][2][j] + part[e][0][3][j];
            float sp = part[e][1][0][j] + part[e][1][1][j] + part[e][1][2][j] + part[e][1][3][j];
            float sq = part[e][2][0][j] + part[e][2][1][j] + part[e][2][2][j] + part[e][2][3][j];
            float av  = tanhmufu(fmaf(amp, walast, sa + ba_r));
            float p1v = tanhmufu(fmaf(ct,  w1last, sp + b1_r));
            float p2v = tanhmufu(fmaf(st,  w2last, sq + b2_r));
            ubuf[e][j] = (av - av * av) * (p1v - p1v * p1v) * (p2v - p2v * p2v);
        } else if (wid >= 6 && t > 0) {
            const int e = wid - 6;
            float ha = hbuf[e][lane], hb = hbuf[e][lane + 32];
            float y0 = ha * woA0 + hb * woB0;
            float y1 = ha * woA1 + hb * woB1;
            #pragma unroll
            for (int off = 16; off; off >>= 1) {
                y0 += __shfl_xor_sync(~0u, y0, off);
                y1 += __shfl_xor_sync(~0u, y1, off);
            }
            if (lane == 0)
                ((float2*)out)[(size_t)(b0 + e) * TB + (t - 1)] =
                    make_float2(y0 + bo0, y1 + bo1);
        }
        __syncthreads();

        // ==== phase 2: f/g u-half partial dots (both elems) ====
        {
            const float4* u0p = (const float4*)&ubuf[0][s * 16];
            const float4* u1p = (const float4*)&ubuf[1][s * 16];
            float cf0 = 0.f, cg0 = 0.f, cf1 = 0.f, cg1 = 0.f;
            #pragma unroll
            for (int r = 0; r < 4; r++) {
                float4 v0 = u0p[r], v1 = u1p[r];
                #pragma unroll
                for (int c = 0; c < 4; c++) {
                    float w_f = wfu[4*r+c], w_g = wgu[4*r+c];
                    float e0 = (c==0)?v0.x:(c==1)?v0.y:(c==2)?v0.z:v0.w;
                    float e1 = (c==0)?v1.x:(c==1)?v1.y:(c==2)?v1.z:v1.w;
                    cf0 = fmaf(w_f, e0, cf0); cf1 = fmaf(w_f, e1, cf1);
                    cg0 = fmaf(w_g, e0, cg0); cg1 = fmaf(w_g, e1, cg1);
                }
            }
            part[0][0][s][j] = cf0;  part[1][0][s][j] = cf1;
            part[0][1][s][j] = cg0;  part[1][1][s][j] = cg1;
        }
        __syncthreads();

        // ==== h-finalize (warps 4-7) ====
        if (tid >= 128) {
            const int e = (tid >> 6) & 1;
            float sf = part[e][0][0][j] + part[e][0][1][j] + part[e][0][2][j] + part[e][0][3][j]
                     + part[e][3][0][j] + part[e][3][1][j] + part[e][3][2][j] + part[e][3][3][j];
            float sg = part[e][1][0][j] + part[e][1][1][j] + part[e][1][2][j] + part[e][1][3][j]
                     + part[e][4][0][j] + part[e][4][1][j] + part[e][4][2][j] + part[e][4][3][j];
            float f = sigmufu(sf + bf_r);
            float g = tanhmufu(sg + bg_r);
            float hold = hbuf[e][j];
            hbuf[e][j] = fmaf(f, hold - g, g);   // f*h + (1-f)*g
        }
        __syncthreads();
    }

    // ---- epilogue: y for t = TB-1 ----
    if (wid >= 6) {
        const int e = wid - 6;
        float ha = hbuf[e][lane], hb = hbuf[e][lane + 32];
        float y0 = ha * woA0 + hb * woB0;
        float y1 = ha * woA1 + hb * woB1;
        #pragma unroll
        for (int off = 16; off; off >>= 1) {
            y0 += __shfl_xor_sync(~0u, y0, off);
            y1 += __shfl_xor_sync(~0u, y1, off);
        }
        if (lane == 0)
            ((float2*)out)[(size_t)(b0 + e) * TB + (TB - 1)] =
                make_float2(y0 + bo0, y1 + bo1);
    }
}

extern "C" void kernel_launch(void* const* d_in, const int* in_sizes, int n_in,
                              void* d_out, int out_size)
{
    const float* x   = (const float*)d_in[0];
    const float* h0  = (const float*)d_in[1];
    const float* Wa  = (const float*)d_in[2];
    const float* ba  = (const float*)d_in[3];
    const float* Wp1 = (const float*)d_in[4];
    const float* bp1 = (const float*)d_in[5];
    const float* Wp2 = (const float*)d_in[6];
    const float* bp2 = (const float*)d_in[7];
    const float* Wf  = (const float*)d_in[8];
    const float* bf  = (const float*)d_in[9];
    const float* Wg  = (const float*)d_in[10];
    const float* bg  = (const float*)d_in[11];
    const float* Wo  = (const float*)d_in[12];
    const float* bo  = (const float*)d_in[13];
    float* out = (float*)d_out;

    pgjanet_kernel<<<128, 256>>>(x, h0, Wa, ba, Wp1, bp1, Wp2, bp2,
                                 Wf, bf, Wg, bg, Wo, bo, out);
}

// round 14
// speedup vs baseline: 1.7428x; 1.0872x over previous
#include <cuda_runtime.h>

// PGJANET recurrent scan: B=256, T=2048, H=64, O=2.
// R13 base (R4 structure + MUFU transcendentals, 1362 us) + 3 chain cuts:
//  1) y-reduction split: seg2 does 2 shuffle levels -> 8 smem partials;
//     seg4's idle warp 0 (lanes 0-3) finishes sum + STG (hidden under h-fin)
//  2) x-scalars (amp/cos/sin) software-pipelined one step ahead in registers
//  3) tree-shaped finalize sums (shorter add chains)

#define TB 2048

__device__ __forceinline__ float tanhmufu(float v) {
    float r; asm("tanh.approx.f32 %0, %1;" : "=f"(r) : "f"(v)); return r;
}
__device__ __forceinline__ float sigmufu(float v) {
    return fmaf(0.5f, tanhmufu(0.5f * v), 0.5f);
}

__global__ void __launch_bounds__(256, 1)
pgjanet_kernel(const float* __restrict__ x,
               const float* __restrict__ h0,
               const float* __restrict__ Wa,  const float* __restrict__ ba,
               const float* __restrict__ Wp1, const float* __restrict__ bp1,
               const float* __restrict__ Wp2, const float* __restrict__ bp2,
               const float* __restrict__ Wf,  const float* __restrict__ bf,
               const float* __restrict__ Wg,  const float* __restrict__ bg,
               const float* __restrict__ Wo,  const float* __restrict__ bo,
               float* __restrict__ out)
{
    __shared__ __align__(16) float2 xb[2][TB];        // 32 KB
    __shared__ __align__(16) float hbuf[2][64];
    __shared__ __align__(16) float ubuf[2][64];
    __shared__ __align__(16) float part[2][5][4][64]; // [elem][gate][slice][unit]
    __shared__ __align__(16) float ypart[2][2][8];    // [elem][out][8 partials]

    const int tid  = threadIdx.x;
    const int lane = tid & 31;
    const int wid  = tid >> 5;
    const int j    = tid & 63;      // hidden unit
    const int s    = tid >> 6;      // k-slice 0..3
    const int b0   = blockIdx.x * 2;

    // ---- weights in registers (112 floats) ----
    float wa[16], wp1[16], wp2[16], wfh[16], wgh[16], wfu[16], wgu[16];
    {
        const float* A = Wa  + j * 65 + s * 16;
        const float* P = Wp1 + j * 65 + s * 16;
        const float* Q = Wp2 + j * 65 + s * 16;
        const float* F = Wf  + j * 128 + s * 16;
        const float* G = Wg  + j * 128 + s * 16;
        #pragma unroll
        for (int i = 0; i < 16; i++) {
            wa[i]  = A[i];  wp1[i] = P[i];  wp2[i] = Q[i];
            wfh[i] = F[i];  wgh[i] = G[i];
            wfu[i] = F[64 + i]; wgu[i] = G[64 + i];
        }
    }

    // ---- finalize constants ----
    float walast = 0.f, w1last = 0.f, w2last = 0.f, ba_r = 0.f, b1_r = 0.f, b2_r = 0.f;
    if (tid < 128) {                        // u-finalize: (e = tid>>6, j)
        walast = Wa [j * 65 + 64]; ba_r = ba [j];
        w1last = Wp1[j * 65 + 64]; b1_r = bp1[j];
        w2last = Wp2[j * 65 + 64]; b2_r = bp2[j];
    }
    float bf_r = 0.f, bg_r = 0.f;
    if (tid >= 128) { bf_r = bf[j]; bg_r = bg[j]; }   // h-finalize: (e=(tid>>6)&1, j)
    float woA0 = 0.f, woB0 = 0.f, woA1 = 0.f, woB1 = 0.f;
    if (wid >= 6) {                         // y stage-1: warps 6,7 -> elem 0,1
        woA0 = Wo[lane];      woB0 = Wo[lane + 32];
        woA1 = Wo[64 + lane]; woB1 = Wo[96 + lane];
    }
    float bo0 = 0.f, bo1 = 0.f;             // needed by warp 0 (y finish) + 6,7 (epilogue)
    if (wid == 0 || wid >= 6) { bo0 = bo[0]; bo1 = bo[1]; }

    // ---- preload x + h0 ----
    {
        const float2* xg0 = (const float2*)x + (size_t)b0 * TB;
        const float2* xg1 = (const float2*)x + (size_t)(b0 + 1) * TB;
        for (int i = tid; i < TB; i += 256) { xb[0][i] = xg0[i]; xb[1][i] = xg1[i]; }
    }
    if (tid < 128) hbuf[tid >> 6][j] = h0[(size_t)(b0 + (tid >> 6)) * 64 + j];
    __syncthreads();

    // ---- x-scalar pipeline registers (u-fin threads), seeded for t=0 ----
    float ampP = 0.f, ctP = 1.f, stP = 0.f;
    if (tid < 128) {
        const int e = tid >> 6;
        float2 xv = xb[e][0];
        float s2 = fmaf(xv.x, xv.x, xv.y * xv.y);
        float ri = rsqrtf(s2);
        bool nz = (s2 > 0.f);
        ampP = nz ? s2 * ri : 0.f;
        ctP  = nz ? xv.x * ri : 1.f;
        stP  = nz ? xv.y * ri : 0.f;
    }

    #pragma unroll 1
    for (int t = 0; t < TB; t++) {
        // ==== phase 1: a/p1/p2 + f/g h-half partial dots (both elems) ====
        {
            const float4* h0p = (const float4*)&hbuf[0][s * 16];
            const float4* h1p = (const float4*)&hbuf[1][s * 16];
            float a0 = 0.f, p0 = 0.f, q0 = 0.f, f0 = 0.f, g0 = 0.f;
            float a1 = 0.f, p1 = 0.f, q1 = 0.f, f1 = 0.f, g1 = 0.f;
            #pragma unroll
            for (int r = 0; r < 4; r++) {
                float4 v0 = h0p[r], v1 = h1p[r];
                #pragma unroll
                for (int c = 0; c < 4; c++) {
                    float w_a = wa[4*r+c], w_p = wp1[4*r+c], w_q = wp2[4*r+c];
                    float w_f = wfh[4*r+c], w_g = wgh[4*r+c];
                    float e0 = (c==0)?v0.x:(c==1)?v0.y:(c==2)?v0.z:v0.w;
                    float e1 = (c==0)?v1.x:(c==1)?v1.y:(c==2)?v1.z:v1.w;
                    a0 = fmaf(w_a, e0, a0); a1 = fmaf(w_a, e1, a1);
                    p0 = fmaf(w_p, e0, p0); p1 = fmaf(w_p, e1, p1);
                    q0 = fmaf(w_q, e0, q0); q1 = fmaf(w_q, e1, q1);
                    f0 = fmaf(w_f, e0, f0); f1 = fmaf(w_f, e1, f1);
                    g0 = fmaf(w_g, e0, g0); g1 = fmaf(w_g, e1, g1);
                }
            }
            part[0][0][s][j] = a0;  part[1][0][s][j] = a1;
            part[0][1][s][j] = p0;  part[1][1][s][j] = p1;
            part[0][2][s][j] = q0;  part[1][2][s][j] = q1;
            part[0][3][s][j] = f0;  part[1][3][s][j] = f1;
            part[0][4][s][j] = g0;  part[1][4][s][j] = g1;
        }
        __syncthreads();   // #1

        // ==== seg2: u-finalize (warps 0-3) || y stage-1 (warps 6-7) ====
        if (tid < 128) {
            const int e = tid >> 6;
            float sa = (part[e][0][0][j] + part[e][0][1][j])
                     + (part[e][0][2][j] + part[e][0][3][j]);
            float sp = (part[e][1][0][j] + part[e][1][1][j])
                     + (part[e][1][2][j] + part[e][1][3][j]);
            float sq = (part[e][2][0][j] + part[e][2][1][j])
                     + (part[e][2][2][j] + part[e][2][3][j]);
            float av  = tanhmufu(fmaf(ampP, walast, sa + ba_r));
            float p1v = tanhmufu(fmaf(ctP,  w1last, sp + b1_r));
            float p2v = tanhmufu(fmaf(stP,  w2last, sq + b2_r));
            ubuf[e][j] = (av - av * av) * (p1v - p1v * p1v) * (p2v - p2v * p2v);
            // pipeline x-scalars for step t+1 (issues hide in tanh shadow)
            int tn = (t + 1 < TB) ? t + 1 : t;
            float2 xv = xb[e][tn];
            float s2 = fmaf(xv.x, xv.x, xv.y * xv.y);
            float ri = rsqrtf(s2);
            bool nz = (s2 > 0.f);
            ampP = nz ? s2 * ri : 0.f;
            ctP  = nz ? xv.x * ri : 1.f;
            stP  = nz ? xv.y * ri : 0.f;
        } else if (wid >= 6 && t > 0) {
            // y stage-1 for y_{t-1}: 2 shuffle levels -> 8 partials to smem
            const int e = wid - 6;
            float ha = hbuf[e][lane], hb = hbuf[e][lane + 32];
            float y0 = fmaf(ha, woA0, hb * woB0);
            float y1 = fmaf(ha, woA1, hb * woB1);
            y0 += __shfl_xor_sync(~0u, y0, 16);
            y1 += __shfl_xor_sync(~0u, y1, 16);
            y0 += __shfl_xor_sync(~0u, y0, 8);
            y1 += __shfl_xor_sync(~0u, y1, 8);
            if (lane < 8) { ypart[e][0][lane] = y0; ypart[e][1][lane] = y1; }
        }
        __syncthreads();   // #2

        // ==== phase 2: f/g u-half partial dots (both elems) ====
        {
            const float4* u0p = (const float4*)&ubuf[0][s * 16];
            const float4* u1p = (const float4*)&ubuf[1][s * 16];
            float cf0 = 0.f, cg0 = 0.f, cf1 = 0.f, cg1 = 0.f;
            #pragma unroll
            for (int r = 0; r < 4; r++) {
                float4 v0 = u0p[r], v1 = u1p[r];
                #pragma unroll
                for (int c = 0; c < 4; c++) {
                    float w_f = wfu[4*r+c], w_g = wgu[4*r+c];
                    float e0 = (c==0)?v0.x:(c==1)?v0.y:(c==2)?v0.z:v0.w;
                    float e1 = (c==0)?v1.x:(c==1)?v1.y:(c==2)?v1.z:v1.w;
                    cf0 = fmaf(w_f, e0, cf0); cf1 = fmaf(w_f, e1, cf1);
                    cg0 = fmaf(w_g, e0, cg0); cg1 = fmaf(w_g, e1, cg1);
                }
            }
            part[0][0][s][j] = cf0;  part[1][0][s][j] = cf1;
            part[0][1][s][j] = cg0;  part[1][1][s][j] = cg1;
        }
        __syncthreads();   // #3

        // ==== seg4: h-finalize (warps 4-7) || y finish (warp 0, lanes 0-3) ====
        if (tid >= 128) {
            const int e = (tid >> 6) & 1;
            float sf = ((part[e][0][0][j] + part[e][0][1][j])
                      + (part[e][0][2][j] + part[e][0][3][j]))
                     + ((part[e][3][0][j] + part[e][3][1][j])
                      + (part[e][3][2][j] + part[e][3][3][j]));
            float sg = ((part[e][1][0][j] + part[e][1][1][j])
                      + (part[e][1][2][j] + part[e][1][3][j]))
                     + ((part[e][4][0][j] + part[e][4][1][j])
                      + (part[e][4][2][j] + part[e][4][3][j]));
            float f = sigmufu(sf + bf_r);
            float g = tanhmufu(sg + bg_r);
            float hold = hbuf[e][j];
            hbuf[e][j] = fmaf(f, hold - g, g);   // f*h + (1-f)*g
        } else if (wid == 0 && lane < 4 && t > 0) {
            // finish y_{t-1}: lane -> (e = lane>>1, o = lane&1)
            const int e = lane >> 1, o = lane & 1;
            const float4* yp = (const float4*)&ypart[e][o][0];
            float4 va = yp[0], vb = yp[1];
            float sum = ((va.x + va.y) + (va.z + va.w))
                      + ((vb.x + vb.y) + (vb.z + vb.w));
            out[(((size_t)(b0 + e) * TB) + (t - 1)) * 2 + o] =
                sum + (o ? bo1 : bo0);
        }
        __syncthreads();   // #4
    }

    // ---- epilogue: y for t = TB-1 (full reduction on warps 6-7) ----
    if (wid >= 6) {
        const int e = wid - 6;
        float ha = hbuf[e][lane], hb = hbuf[e][lane + 32];
        float y0 = fmaf(ha, woA0, hb * woB0);
        float y1 = fmaf(ha, woA1, hb * woB1);
        #pragma unroll
        for (int off = 16; off; off >>= 1) {
            y0 += __shfl_xor_sync(~0u, y0, off);
            y1 += __shfl_xor_sync(~0u, y1, off);
        }
        if (lane == 0)
            ((float2*)out)[(size_t)(b0 + e) * TB + (TB - 1)] =
                make_float2(y0 + bo0, y1 + bo1);
    }
}

extern "C" void kernel_launch(void* const* d_in, const int* in_sizes, int n_in,
                              void* d_out, int out_size)
{
    const float* x   = (const float*)d_in[0];
    const float* h0  = (const float*)d_in[1];
    const float* Wa  = (const float*)d_in[2];
    const float* ba  = (const float*)d_in[3];
    const float* Wp1 = (const float*)d_in[4];
    const float* bp1 = (const float*)d_in[5];
    const float* Wp2 = (const float*)d_in[6];
    const float* bp2 = (const float*)d_in[7];
    const float* Wf  = (const float*)d_in[8];
    const float* bf  = (const float*)d_in[9];
    const float* Wg  = (const float*)d_in[10];
    const float* bg  = (const float*)d_in[11];
    const float* Wo  = (const float*)d_in[12];
    const float* bo  = (const float*)d_in[13];
    float* out = (float*)d_out;

    pgjanet_kernel<<<128, 256>>>(x, h0, Wa, ba, Wp1, bp1, Wp2, bp2,
                                 Wf, bf, Wg, bg, Wo, bo, out);
}